// round 16
// baseline (speedup 1.0000x reference)
#include <cuda_runtime.h>
#include <cuda_fp16.h>
#include <cstdint>

// ---------------- problem constants ----------------
#define B_    8
#define L_    1024
#define K_    30
#define EF_   128          // EDGE_FEATURES (= N)
#define EIN_  416          // NUM_PE + NUM_RBF*25 (= K)
#define KPAD_ 448          // K padded to 7*64
#define NPE_  16
#define PEC_  66           // 2*MAX_REL+2
#define NEDGE (B_*L_*K_)   // 245760

// ---------------- edge-kernel tiling ----------------
#define EB_   128          // edges per block (= M)
#define KC_   64           // k per chunk (= 128 bytes/row fp16)
#define NCH_  7            // KPAD_/KC_
#define ATSZ_ 16384        // A tile: 128 rows * 128B
#define BTSZ_ 16384        // B tile: 128 rows * 128B
#define BUFSZ_ (ATSZ_ + BTSZ_)       // 32768 per buffer (A, B)

// ---------------- scratch (static device globals) ----------------
__device__ float  g_X5[B_*L_*15];
__device__ float4 g_Ca[B_*L_];       // compacted {Ca.xyz, mask} for topk
__device__ int    g_Eidx[NEDGE];
__device__ __half g_Wh[EF_*KPAD_];   // W_edge fp16, [n][k] k-major, zero-padded

// ================= helpers =================
__device__ __forceinline__ uint32_t smem_u32(const void* p) {
    uint32_t a;
    asm("{ .reg .u64 t; cvta.to.shared.u64 t, %1; cvt.u32.u64 %0, t; }" : "=r"(a) : "l"(p));
    return a;
}
__device__ __forceinline__ void sts128(uint32_t addr, uint32_t a, uint32_t b, uint32_t c, uint32_t d) {
    asm volatile("st.shared.v4.b32 [%0], {%1,%2,%3,%4};" :: "r"(addr), "r"(a), "r"(b), "r"(c), "r"(d) : "memory");
}
__device__ __forceinline__ void ldsm4(uint32_t* r, uint32_t addr) {
    asm volatile("ldmatrix.sync.aligned.m8n8.x4.shared.b16 {%0,%1,%2,%3}, [%4];"
        : "=r"(r[0]), "=r"(r[1]), "=r"(r[2]), "=r"(r[3]) : "r"(addr));
}
__device__ __forceinline__ void mma16816(float (&d)[4], const uint32_t* a, const uint32_t* b) {
    asm volatile("mma.sync.aligned.m16n8k16.row.col.f32.f16.f16.f32 "
        "{%0,%1,%2,%3}, {%4,%5,%6,%7}, {%8,%9}, {%0,%1,%2,%3};"
        : "+f"(d[0]), "+f"(d[1]), "+f"(d[2]), "+f"(d[3])
        : "r"(a[0]), "r"(a[1]), "r"(a[2]), "r"(a[3]), "r"(b[0]), "r"(b[1]));
}
__device__ __forceinline__ uint32_t pkh2(float a, float b) {
    __half2 h = __floats2half2_rn(a, b);    // low = a
    return *(uint32_t*)&h;
}
__device__ __forceinline__ void cpasync16(uint32_t dst, const void* src) {
    asm volatile("cp.async.cg.shared.global [%0], [%1], 16;" :: "r"(dst), "l"(src) : "memory");
}
#define CP_COMMIT() asm volatile("cp.async.commit_group;" ::: "memory")
#define CP_WAIT0()  asm volatile("cp.async.wait_group 0;" ::: "memory")

// ================= kernel 1: fused X5 + Ca-compact + X passthrough + W->fp16 =================
__global__ void prep_kernel(const float* __restrict__ X, const float* __restrict__ W,
                            const float* __restrict__ mask, float* __restrict__ outX) {
    int t = blockIdx.x * blockDim.x + threadIdx.x;
    if (t < B_*L_) {
        const float* x = X + (size_t)t * 12;
        float x0x=x[0], x0y=x[1],  x0z=x[2];
        float x1x=x[3], x1y=x[4],  x1z=x[5];
        float x2x=x[6], x2y=x[7],  x2z=x[8];
        float bx=x1x-x0x, by=x1y-x0y, bz=x1z-x0z;
        float cx=x2x-x1x, cy=x2y-x1y, cz=x2z-x1z;
        float ax=by*cz-bz*cy, ay=bz*cx-bx*cz, az=bx*cy-by*cx;
        float* o = g_X5 + t*15;
        #pragma unroll
        for (int i = 0; i < 12; i++) { o[i] = x[i]; outX[(size_t)t*12 + i] = x[i]; }
        o[12] = -0.58273431f*ax + 0.56802827f*bx - 0.54067466f*cx + x1x;
        o[13] = -0.58273431f*ay + 0.56802827f*by - 0.54067466f*cy + x1y;
        o[14] = -0.58273431f*az + 0.56802827f*bz - 0.54067466f*cz + x1z;
        g_Ca[t] = make_float4(x1x, x1y, x1z, mask[t]);
    }
    if (t < EF_*KPAD_) {
        int n = t / KPAD_, k = t % KPAD_;
        float w = (k < EIN_) ? W[n*EIN_ + k] : 0.0f;
        g_Wh[t] = __float2half_rn(w);
    }
}

// ================= kernel 2: radix-select top-30 (compacted Ca loads) =================
#define NBIN_ 4096
__global__ __launch_bounds__(256) void topk_kernel(float* __restrict__ outEidxF) {
    __shared__ __align__(16) unsigned int hist[NBIN_];   // 16 KB
    __shared__ float sMaxW[8];
    __shared__ int   sWS[8];
    __shared__ int   sT, sCnt[2];
    __shared__ unsigned long long defL[32];
    __shared__ unsigned long long tieL[320];

    int bi = blockIdx.x;
    int b  = bi >> 10;
    int tid = threadIdx.x, lane = tid & 31, warp = tid >> 5;

    const float4* cb = g_Ca + (size_t)b * L_;
    int il = bi & (L_-1);
    float4 ci = cb[il];
    float mi = ci.w;

    float Dv[4], m2v[4];
    float lmax = -1e30f;
    #pragma unroll
    for (int r = 0; r < 4; r++) {
        int j = tid + r*256;
        float4 cj = cb[j];
        float dx = ci.x - cj.x, dy = ci.y - cj.y, dz = ci.z - cj.z;
        float m2 = mi * cj.w;
        float D  = m2 * sqrtf(dx*dx + dy*dy + dz*dz + 1e-6f);
        Dv[r] = D; m2v[r] = m2;
        lmax = fmaxf(lmax, D);
    }
    #pragma unroll
    for (int off = 16; off; off >>= 1)
        lmax = fmaxf(lmax, __shfl_xor_sync(0xffffffffu, lmax, off));
    if (lane == 0) sMaxW[warp] = lmax;

    // zero histogram (uint4) + counters while max lands
    {
        uint4 z = make_uint4(0,0,0,0);
        uint4* h4 = (uint4*)hist;
        #pragma unroll
        for (int u = 0; u < NBIN_/4/256; u++) h4[tid + u*256] = z;
    }
    if (tid == 0) { sCnt[0] = 0; sCnt[1] = 0; }
    __syncthreads();
    if (tid == 0) {
        float m = sMaxW[0];
        #pragma unroll
        for (int w = 1; w < 8; w++) m = fmaxf(m, sMaxW[w]);
        sMaxW[0] = m;
    }
    __syncthreads();
    float Dmax = sMaxW[0];

    unsigned long long keys[4];
    #pragma unroll
    for (int r = 0; r < 4; r++) {
        float adj = Dv[r] + (1.0f - m2v[r]) * Dmax;
        keys[r] = ((unsigned long long)__float_as_uint(adj) << 32) | (unsigned)(tid + r*256);
        atomicAdd(&hist[(uint32_t)(keys[r] >> 51)], 1u);
    }
    __syncthreads();

    // prefix scan of 256 per-thread partial sums (16 bins each)
    int s = 0;
    #pragma unroll
    for (int u = 0; u < 16; u++) s += (int)hist[tid*16 + u];
    int inc = s;
    #pragma unroll
    for (int off = 1; off < 32; off <<= 1) {
        int v = __shfl_up_sync(0xffffffffu, inc, off);
        if (lane >= off) inc += v;
    }
    if (lane == 31) sWS[warp] = inc;
    __syncthreads();
    if (tid == 0) {
        int acc = 0;
        #pragma unroll
        for (int w = 0; w < 8; w++) { int v = sWS[w]; sWS[w] = acc; acc += v; }
    }
    __syncthreads();
    int excl = inc - s + sWS[warp];
    if (excl < K_ && excl + s >= K_) {
        int c = excl;
        #pragma unroll 1
        for (int u = 0; u < 16; u++) {
            int h = (int)hist[tid*16 + u];
            if (c + h >= K_) { sT = tid*16 + u; break; }
            c += h;
        }
    }
    __syncthreads();
    uint32_t tb = (uint32_t)sT;

    // collect definite (<30) and tie candidates
    #pragma unroll
    for (int r = 0; r < 4; r++) {
        uint32_t bn = (uint32_t)(keys[r] >> 51);
        if (bn < tb) {
            int p = atomicAdd(&sCnt[0], 1);
            defL[p] = keys[r];
        } else if (bn == tb) {
            int p = atomicAdd(&sCnt[1], 1);
            if (p < 320) tieL[p] = keys[r];
        }
    }
    __syncthreads();

    int dc = sCnt[0];
    int tc = sCnt[1] < 320 ? sCnt[1] : 320;
    if (tid < dc) {
        unsigned long long k = defL[tid];
        int r = 0;
        for (int j2 = 0; j2 < dc; j2++) r += (defL[j2] < k);
        int j = (int)(k & 0xffffffffu);
        g_Eidx[bi*K_ + r]   = j;
        outEidxF[bi*K_ + r] = (float)j;
    }
    if (tid < tc) {
        unsigned long long k = tieL[tid];
        int r = 0;
        for (int j2 = 0; j2 < tc; j2++) r += (tieL[j2] < k);
        int slot = dc + r;
        if (slot < K_) {
            int j = (int)(k & 0xffffffffu);
            g_Eidx[bi*K_ + slot]   = j;
            outEidxF[bi*K_ + slot] = (float)j;
        }
    }
}

// ================= kernel 3: HMMA edge kernel (fp16, m32n64 warp tiles) =================
// 128 edges/block, 256 threads, 2 CTAs/SM (~88KB smem). XOR-swizzled 128B rows.
// 8 warps = 4 m-tiles (m32) x 2 n-halves (n64): per ks, 6 ldsm.x4 feed 16 MMAs
// (2x the arithmetic intensity per smem byte of the R13-R15 2x4 layout).
// Double-buffered, one __syncthreads per chunk; LN epilogue stores direct to global.

// smem offsets (bytes)
#define SM_RED   0        // 128*4 floats = 2048
#define SM_SD    2048     // 512
#define SM_SI    2560     // 512
#define SM_SN    3072     // 512
#define SM_WPE   3584     // 4224 -> 7808
#define SM_BPE   7808     // 64
#define SM_LNW   7872     // 512
#define SM_LNB   8384     // 512 -> 8896
#define SM_DIST  8896     // 128*25*4 = 12800 -> 21696
#define SM_TILES 22528    // 2 buffers * 32768 = 65536
#define SMEM_BYTES (SM_TILES + 2*BUFSZ_)   // 88064

#define SWO(r, c) ((uint32_t)((r)*128 + (((c) ^ ((r) & 7)) << 4)))

__device__ __forceinline__ void gen16(int pr, int sde,
                                      const float* __restrict__ Wpe_s,
                                      const float* __restrict__ bpe_s,
                                      const float* __restrict__ dist_e,
                                      float* v) {
    if (pr < 0) {
        #pragma unroll
        for (int u = 0; u < 16; u++) v[u] = Wpe_s[u*PEC_ + sde] + bpe_s[u];
    } else if (pr < 25) {
        const float s  = 1.06666672f;      // 0.8 * 20/15
        const float s2 = 1.13777781f;      // s^2
        const float cc = 0.10273956f;      // exp(-2*s^2)
        float d = dist_e[pr];
        if (d < 12.5f) {
            float t0 = (d - 2.0f) * 0.8f;
            float e = __expf(-t0*t0);
            float r = __expf(2.0f*s*t0 - s2);
            v[0] = e;
            #pragma unroll
            for (int m = 1; m < 16; m++) { e *= r; r *= cc; v[m] = e; }
        } else {
            float t15 = (d - 22.0f) * 0.8f;
            float e = __expf(-t15*t15);
            float sg = __expf(-2.0f*s*t15 - s2);
            v[15] = e;
            #pragma unroll
            for (int m = 14; m >= 0; m--) { e *= sg; sg *= cc; v[m] = e; }
        }
    } else {
        #pragma unroll
        for (int u = 0; u < 16; u++) v[u] = 0.0f;
    }
}

__global__ __launch_bounds__(256, 2) void edge_kernel(
    const int*   __restrict__ ridx,
    const int*   __restrict__ clab,
    const float* __restrict__ W_pe,
    const float* __restrict__ b_pe,
    const float* __restrict__ ln_w,
    const float* __restrict__ ln_b,
    float*       __restrict__ outE)
{
    extern __shared__ char smem[];
    uint32_t sb = smem_u32(smem);
    int tid = threadIdx.x, lane = tid & 31, wid = tid >> 5;
    int blk = blockIdx.x;

    float* red    = (float*)(smem + SM_RED);
    int*   sd     = (int*)  (smem + SM_SD);
    int*   sI     = (int*)  (smem + SM_SI);
    int*   sN     = (int*)  (smem + SM_SN);
    float* Wpe_s  = (float*)(smem + SM_WPE);
    float* bpe_s  = (float*)(smem + SM_BPE);
    float* lnw_s  = (float*)(smem + SM_LNW);
    float* lnb_s  = (float*)(smem + SM_LNB);
    float* dist_s = (float*)(smem + SM_DIST);

    for (int i = tid; i < NPE_*PEC_; i += 256) Wpe_s[i] = W_pe[i];
    if (tid < NPE_) bpe_s[tid] = b_pe[tid];
    if (tid < EF_)  { lnw_s[tid] = ln_w[tid]; lnb_s[tid] = ln_b[tid]; }

    if (tid < EB_) {
        int eg  = blk*EB_ + tid;
        int b   = eg / (L_*K_);
        int r   = eg % (L_*K_);
        int i   = r / K_;
        int nbr = g_Eidx[eg];
        int gi = b*L_ + i, gn = b*L_ + nbr;
        sI[tid] = gi; sN[tid] = gn;
        int off  = ridx[gi] - ridx[gn];
        int same = (clab[gi] == clab[gn]);
        int c = off + 32; c = c < 0 ? 0 : (c > 64 ? 64 : c);
        sd[tid] = same ? c : 65;
    }
    __syncthreads();

    for (int w = tid; w < EB_*25; w += 256) {
        int e = w / 25, p = w % 25;
        int a = p / 5, bb = p % 5;
        const float* xi = g_X5 + sI[e]*15 + a*3;
        const float* xn = g_X5 + sN[e]*15 + bb*3;
        float dx = xi[0]-xn[0], dy = xi[1]-xn[1], dz = xi[2]-xn[2];
        dist_s[w] = sqrtf(dx*dx + dy*dy + dz*dz + 1e-6f);
    }
    __syncthreads();

    // warp layout: mw = m32 tile (0..3), nw = n64 half (0..1)
    int mw = wid >> 1, nw = wid & 1;
    int arow    = mw*32 + ((lane>>3)&1)*8 + (lane&7);
    uint32_t achunk0 = (uint32_t)(lane>>4);
    uint32_t aRowBase = (uint32_t)(arow*128);
    uint32_t aRS      = (uint32_t)(arow & 7);
    int brow_l  = nw*64 + (lane>>4)*8 + (lane&7);
    uint32_t bchunk0 = (uint32_t)((lane>>3)&1);
    uint32_t bRowBase = (uint32_t)(brow_l*128);
    uint32_t bRS      = (uint32_t)(brow_l & 7);

    // A-fill thread mapping: edge fe (0..127), half hh -> k quarters {2hh, 2hh+1}
    int fe = tid >> 1;
    int hh = tid & 1;
    const float* dist_e = dist_s + fe*25;
    int sde = sd[fe];
    uint32_t aFillOff0 = SWO(fe, 4*hh);
    uint32_t aFillOff1 = SWO(fe, 4*hh+1);
    uint32_t aFillOff2 = SWO(fe, 4*hh+2);
    uint32_t aFillOff3 = SWO(fe, 4*hh+3);

    float acc[2][8][4];
    #pragma unroll
    for (int mt = 0; mt < 2; mt++)
        #pragma unroll
        for (int nt = 0; nt < 8; nt++)
            #pragma unroll
            for (int i = 0; i < 4; i++) acc[mt][nt][i] = 0.0f;

    // ---- prologue: B0 via cp.async + fill A0 into buffer 0 ----
    {
        uint32_t bt = sb + SM_TILES + ATSZ_;
        #pragma unroll
        for (int it = 0; it < 4; it++) {
            int i = tid + it*256;
            int n = i >> 3, g = i & 7;
            cpasync16(bt + SWO(n, g), g_Wh + n*KPAD_ + g*8);
        }
        CP_COMMIT();
        uint32_t ah = sb + SM_TILES;
        float v[16];
        uint32_t hw[8];
        gen16(2*hh - 1, sde, Wpe_s, bpe_s, dist_e, v);
        #pragma unroll
        for (int u = 0; u < 8; u++) hw[u] = pkh2(v[2*u], v[2*u+1]);
        sts128(ah + aFillOff0, hw[0], hw[1], hw[2], hw[3]);
        sts128(ah + aFillOff1, hw[4], hw[5], hw[6], hw[7]);
        gen16(2*hh, sde, Wpe_s, bpe_s, dist_e, v);
        #pragma unroll
        for (int u = 0; u < 8; u++) hw[u] = pkh2(v[2*u], v[2*u+1]);
        sts128(ah + aFillOff2, hw[0], hw[1], hw[2], hw[3]);
        sts128(ah + aFillOff3, hw[4], hw[5], hw[6], hw[7]);
        CP_WAIT0();
    }
    __syncthreads();

    // ---- main loop: one sync per chunk ----
    #pragma unroll 1
    for (int c = 0; c < NCH_; c++) {
        uint32_t cur = sb + SM_TILES + (uint32_t)(c & 1) * BUFSZ_;
        uint32_t nxt = sb + SM_TILES + (uint32_t)((c+1) & 1) * BUFSZ_;

        if (c + 1 < NCH_) {
            uint32_t bt = nxt + ATSZ_;
            #pragma unroll
            for (int it = 0; it < 4; it++) {
                int i = tid + it*256;
                int n = i >> 3, g = i & 7;
                cpasync16(bt + SWO(n, g), g_Wh + n*KPAD_ + (c+1)*KC_ + g*8);
            }
            CP_COMMIT();
        }

        uint32_t At = cur, Bt = cur + ATSZ_;
        #pragma unroll
        for (int ks = 0; ks < 4; ks++) {
            uint32_t aOff = aRowBase + ((((uint32_t)(2*ks) + achunk0) ^ aRS) << 4);
            uint32_t bOff = bRowBase + ((((uint32_t)(2*ks) + bchunk0) ^ bRS) << 4);
            uint32_t ah[8], bf[16];
            ldsm4(ah,     At + aOff);
            ldsm4(ah + 4, At + aOff + 2048);
            #pragma unroll
            for (int p = 0; p < 4; p++)
                ldsm4(bf + 4*p, Bt + bOff + (uint32_t)(p*2048));
            #pragma unroll
            for (int mt = 0; mt < 2; mt++)
                #pragma unroll
                for (int nt = 0; nt < 8; nt++)
                    mma16816(acc[mt][nt], ah + 4*mt, bf + 2*nt);
        }

        if (c + 1 < NCH_) {
            float v[16];
            uint32_t hw[8];
            gen16(4*(c+1) + 2*hh - 1, sde, Wpe_s, bpe_s, dist_e, v);
            #pragma unroll
            for (int u = 0; u < 8; u++) hw[u] = pkh2(v[2*u], v[2*u+1]);
            sts128(nxt + aFillOff0, hw[0], hw[1], hw[2], hw[3]);
            sts128(nxt + aFillOff1, hw[4], hw[5], hw[6], hw[7]);
            gen16(4*(c+1) + 2*hh, sde, Wpe_s, bpe_s, dist_e, v);
            #pragma unroll
            for (int u = 0; u < 8; u++) hw[u] = pkh2(v[2*u], v[2*u+1]);
            sts128(nxt + aFillOff2, hw[0], hw[1], hw[2], hw[3]);
            sts128(nxt + aFillOff3, hw[4], hw[5], hw[6], hw[7]);
        }
        CP_WAIT0();
        __syncthreads();
    }

    // ---------------- epilogue: LayerNorm + direct global store ----------------
    int qrow = lane >> 2;
    #pragma unroll
    for (int mt = 0; mt < 2; mt++) {
        #pragma unroll
        for (int h = 0; h < 2; h++) {
            float s = 0.f, sq = 0.f;
            #pragma unroll
            for (int nt = 0; nt < 8; nt++) {
                float v0 = acc[mt][nt][2*h], v1 = acc[mt][nt][2*h+1];
                s += v0 + v1; sq += v0*v0 + v1*v1;
            }
            s  += __shfl_xor_sync(0xffffffffu, s, 1);
            sq += __shfl_xor_sync(0xffffffffu, sq, 1);
            s  += __shfl_xor_sync(0xffffffffu, s, 2);
            sq += __shfl_xor_sync(0xffffffffu, sq, 2);
            if ((lane & 3) == 0) {
                int row = mw*32 + mt*16 + h*8 + qrow;
                red[row*4 + nw*2 + 0] = s;
                red[row*4 + nw*2 + 1] = sq;
            }
        }
    }
    __syncthreads();

    int cq = 2*(lane & 3);
    #pragma unroll
    for (int mt = 0; mt < 2; mt++) {
        #pragma unroll
        for (int h = 0; h < 2; h++) {
            int row = mw*32 + mt*16 + h*8 + qrow;
            float sum = red[row*4 + 0] + red[row*4 + 2];
            float sq  = red[row*4 + 1] + red[row*4 + 3];
            float mean = sum * (1.0f/128.0f);
            float var  = sq * (1.0f/128.0f) - mean*mean;
            float rstd = rsqrtf(var + 1e-5f);
            float* orow = outE + (size_t)(blk*EB_ + row) * EF_ + nw*64 + cq;
            #pragma unroll
            for (int nt = 0; nt < 8; nt++) {
                int col = nw*64 + nt*8 + cq;
                float2 lw = *(float2*)(lnw_s + col);
                float2 lb = *(float2*)(lnb_s + col);
                float2 o;
                o.x = (acc[mt][nt][2*h]   - mean)*rstd*lw.x + lb.x;
                o.y = (acc[mt][nt][2*h+1] - mean)*rstd*lw.y + lb.y;
                *(float2*)(orow + nt*8) = o;
            }
        }
    }
}

// ---------------------------------------------------------------------------
extern "C" void kernel_launch(void* const* d_in, const int* in_sizes, int n_in,
                              void* d_out, int out_size) {
    (void)in_sizes; (void)n_in; (void)out_size;
    const float* X      = (const float*)d_in[0];
    const float* mask   = (const float*)d_in[1];
    const int*   ridx   = (const int*)  d_in[2];
    const int*   clab   = (const int*)  d_in[3];
    const float* W_pe   = (const float*)d_in[4];
    const float* b_pe   = (const float*)d_in[5];
    const float* W_edge = (const float*)d_in[6];
    const float* ln_w   = (const float*)d_in[7];
    const float* ln_b   = (const float*)d_in[8];

    float* out      = (float*)d_out;
    float* outE     = out;                                   // B*L*K*128
    float* outEidxF = out + (size_t)NEDGE * EF_;             // B*L*K (as float)
    float* outX     = outEidxF + (size_t)NEDGE;              // B*L*4*3

    cudaFuncSetAttribute(edge_kernel, cudaFuncAttributeMaxDynamicSharedMemorySize, SMEM_BYTES);

    prep_kernel<<<(EF_*KPAD_ + 255)/256, 256>>>(X, W_edge, mask, outX);
    topk_kernel<<<B_*L_, 256>>>(outEidxF);
    edge_kernel<<<NEDGE/EB_, 256, SMEM_BYTES>>>(ridx, clab, W_pe, b_pe, ln_w, ln_b, outE);
}